// round 1
// baseline (speedup 1.0000x reference)
#include <cuda_runtime.h>
#include <math_constants.h>

// Problem geometry
#define NSRC 16384
#define NTAR 16384
#define NSPLIT 32                       // source splits
#define SRC_PER_SPLIT (NSRC / NSPLIT)   // 512
#define TB 16                           // target blocks
#define TAR_PER_BLOCK (NTAR / TB)       // 1024
#define NTHREADS 256
#define T_PER_THREAD 4                  // register-blocked targets per thread
#define RED_BLOCKS (NTAR / NTHREADS)    // 64

// Scratch (allocation-free rule: __device__ globals)
__device__ float4 g_src4[NSRC];                 // (x, y, z, -0.5*||s||^2)
__device__ float  g_vmax[NSPLIT * NTAR];        // per-split per-target max of (t.s - 0.5 s^2)
__device__ float  g_partial[RED_BLOCKS];        // per-block partial sums

// ---------------------------------------------------------------------------
// Pass 0: pack sources as float4 with fused -0.5*||s||^2
// ---------------------------------------------------------------------------
__global__ void prep_src_kernel(const float* __restrict__ src) {
    int i = blockIdx.x * blockDim.x + threadIdx.x;
    if (i < NSRC) {
        float x = src[3 * i + 0];
        float y = src[3 * i + 1];
        float z = src[3 * i + 2];
        float w = -0.5f * (x * x + y * y + z * z);
        g_src4[i] = make_float4(x, y, z, w);
    }
}

// ---------------------------------------------------------------------------
// Pass 1: main pairwise pass. grid = (TB, NSPLIT).
// Each block: its source split (512 float4, 8KB smem) vs 1024 targets,
// 4 targets register-blocked per thread. Inner loop: 3 FFMA + 1 FMNMX per pair.
// Source smem reads are warp-uniform -> broadcast (conflict-free, ~free).
// ---------------------------------------------------------------------------
__global__ __launch_bounds__(NTHREADS) void nn_main_kernel(const float* __restrict__ tar) {
    __shared__ float4 s_src[SRC_PER_SPLIT];

    const int tb    = blockIdx.x;
    const int split = blockIdx.y;

    // Stage this split's sources into shared memory
    const float4* src = g_src4 + split * SRC_PER_SPLIT;
    for (int j = threadIdx.x; j < SRC_PER_SPLIT; j += NTHREADS)
        s_src[j] = src[j];
    __syncthreads();

    const int t0 = tb * TAR_PER_BLOCK + threadIdx.x;

    float tx[T_PER_THREAD], ty[T_PER_THREAD], tz[T_PER_THREAD], m[T_PER_THREAD];
#pragma unroll
    for (int k = 0; k < T_PER_THREAD; k++) {
        int t = t0 + k * NTHREADS;
        tx[k] = tar[3 * t + 0];
        ty[k] = tar[3 * t + 1];
        tz[k] = tar[3 * t + 2];
        m[k]  = -CUDART_INF_F;
    }

#pragma unroll 4
    for (int j = 0; j < SRC_PER_SPLIT; j++) {
        float4 p = s_src[j];
#pragma unroll
        for (int k = 0; k < T_PER_THREAD; k++) {
            // v = t.s - 0.5*||s||^2 ; argmax v == argmin ||t-s||^2
            float v = fmaf(tx[k], p.x, fmaf(ty[k], p.y, fmaf(tz[k], p.z, p.w)));
            m[k] = fmaxf(m[k], v);
        }
    }

#pragma unroll
    for (int k = 0; k < T_PER_THREAD; k++)
        g_vmax[split * NTAR + t0 + k * NTHREADS] = m[k];
}

// ---------------------------------------------------------------------------
// Pass 2: combine splits, add 0.5*||t||^2, block-reduce (deterministic order)
// ---------------------------------------------------------------------------
__global__ __launch_bounds__(NTHREADS) void nn_reduce_kernel(const float* __restrict__ tar) {
    __shared__ float red[NTHREADS];
    const int t = blockIdx.x * NTHREADS + threadIdx.x;

    float vm = -CUDART_INF_F;
#pragma unroll
    for (int s = 0; s < NSPLIT; s++)
        vm = fmaxf(vm, g_vmax[s * NTAR + t]);

    float x = tar[3 * t + 0];
    float y = tar[3 * t + 1];
    float z = tar[3 * t + 2];
    // 0.5*||t||^2 - max_s(t.s - 0.5||s||^2) == 0.5*min_s ||t - s||^2
    float c = fmaf(0.5f * x, x, fmaf(0.5f * y, y, fmaf(0.5f * z, z, -vm)));

    red[threadIdx.x] = c;
    __syncthreads();
#pragma unroll
    for (int stride = NTHREADS / 2; stride > 0; stride >>= 1) {
        if (threadIdx.x < stride)
            red[threadIdx.x] += red[threadIdx.x + stride];
        __syncthreads();
    }
    if (threadIdx.x == 0)
        g_partial[blockIdx.x] = red[0];
}

// ---------------------------------------------------------------------------
// Pass 3: fixed-order final sum (bitwise deterministic)
// ---------------------------------------------------------------------------
__global__ void nn_final_kernel(float* __restrict__ out) {
    if (threadIdx.x == 0) {
        float s = 0.0f;
        for (int i = 0; i < RED_BLOCKS; i++)
            s += g_partial[i];
        out[0] = s;
    }
}

extern "C" void kernel_launch(void* const* d_in, const int* in_sizes, int n_in,
                              void* d_out, int out_size) {
    const float* src = (const float*)d_in[0];   // src_V [16384,3]
    const float* tar = (const float*)d_in[1];   // tar_V [16384,3]
    float* out = (float*)d_out;

    prep_src_kernel<<<(NSRC + NTHREADS - 1) / NTHREADS, NTHREADS>>>(src);

    dim3 grid(TB, NSPLIT);
    nn_main_kernel<<<grid, NTHREADS>>>(tar);

    nn_reduce_kernel<<<RED_BLOCKS, NTHREADS>>>(tar);
    nn_final_kernel<<<1, 32>>>(out);
}